// round 10
// baseline (speedup 1.0000x reference)
#include <cuda_runtime.h>
#include <cuda_fp16.h>
#include <cstdint>

// ============================================================================
// out[8192,2048] = x[8192,2048] @ W[2048,2048]^T + bias
// fp16 single-term GEMM on HMMA (mma.sync m16n8k16.f32.f16.f16.f32).
// R10: wave-quantization fix — 1 CTA/SM, 7 waves (1.2% quant loss vs 13.5%).
//   CTA 128x128x128: 256 thr, warp grid 4x2, warp tile 32x64,
//   3-stage cp.async, 64KB/stage (two 32KB k-halves) = 192KB -> 1 CTA/SM.
//   16 barriers instead of 32. Stage-head reorder kept from R9.
// ============================================================================

#define M_TOTAL 8192
#define N_TOTAL 2048
#define K_TOTAL 2048

#define MT 128
#define NT 128
#define KT 128                  // K elems per stage (2 x 64-elem halves)
#define KITERS (K_TOTAL / KT)   // 16
#define NSTAGE 3

#define M_TILES (M_TOTAL / MT)  // 64
#define N_TILES (N_TOTAL / NT)  // 16

// stage layout: [A_h0 16K][A_h1 16K][B_h0 16K][B_h1 16K]
#define OFF_B 32768
#define HALF_BYTES 16384
#define STAGE_BYTES 65536
#define SMEM_REQ (NSTAGE * STAGE_BYTES)   // 196608

__device__ __half g_xh[M_TOTAL * K_TOTAL];
__device__ __half g_wh[N_TOTAL * K_TOTAL];

// ---------------------------------------------------------------------------
__device__ __forceinline__ uint32_t smem_u32(const void* p) {
    uint32_t a;
    asm("{ .reg .u64 t; cvta.to.shared.u64 t, %1; cvt.u32.u64 %0, t; }"
        : "=r"(a) : "l"(p));
    return a;
}

__device__ __forceinline__ void cp_async16(uint32_t dst, const void* src) {
    asm volatile("cp.async.cg.shared.global [%0], [%1], 16;"
                 :: "r"(dst), "l"(src));
}
#define CP_COMMIT() asm volatile("cp.async.commit_group;" ::: "memory")
#define CP_WAIT1()  asm volatile("cp.async.wait_group 1;" ::: "memory")

__device__ __forceinline__ void ldsm_x4(uint32_t* r, uint32_t addr) {
    asm volatile("ldmatrix.sync.aligned.m8n8.x4.shared.b16 {%0,%1,%2,%3}, [%4];"
                 : "=r"(r[0]), "=r"(r[1]), "=r"(r[2]), "=r"(r[3])
                 : "r"(addr));
}

__device__ __forceinline__ void mma16816(float* c, const uint32_t* a, const uint32_t* b) {
    asm volatile(
        "mma.sync.aligned.m16n8k16.row.col.f32.f16.f16.f32 "
        "{%0,%1,%2,%3}, {%4,%5,%6,%7}, {%8,%9}, {%0,%1,%2,%3};"
        : "+f"(c[0]), "+f"(c[1]), "+f"(c[2]), "+f"(c[3])
        : "r"(a[0]), "r"(a[1]), "r"(a[2]), "r"(a[3]),
          "r"(b[0]), "r"(b[1]));
}

// ---------------------------------------------------------------------------
// Kernel 1: convert fp32 -> fp16 for BOTH x and W in one launch.
// ---------------------------------------------------------------------------
__global__ void __launch_bounds__(256) convert_both_kernel(
    const float4* __restrict__ srcx, float4* __restrict__ dstx, int n16x,
    const float4* __restrict__ srcw, float4* __restrict__ dstw, int n16w)
{
    int i = blockIdx.x * blockDim.x + threadIdx.x;
    const float4* src;
    float4* dst;
    if (i < n16x) {
        src = srcx + 4 * (size_t)i;
        dst = dstx + 2 * (size_t)i;
    } else {
        int j = i - n16x;
        if (j >= n16w) return;
        src = srcw + 4 * (size_t)j;
        dst = dstw + 2 * (size_t)j;
    }
    float4 v0 = src[0];
    float4 v1 = src[1];
    float4 v2 = src[2];
    float4 v3 = src[3];

    __half2 h0 = __halves2half2(__float2half_rn(v0.x), __float2half_rn(v0.y));
    __half2 h1 = __halves2half2(__float2half_rn(v0.z), __float2half_rn(v0.w));
    __half2 h2 = __halves2half2(__float2half_rn(v1.x), __float2half_rn(v1.y));
    __half2 h3 = __halves2half2(__float2half_rn(v1.z), __float2half_rn(v1.w));
    __half2 h4 = __halves2half2(__float2half_rn(v2.x), __float2half_rn(v2.y));
    __half2 h5 = __halves2half2(__float2half_rn(v2.z), __float2half_rn(v2.w));
    __half2 h6 = __halves2half2(__float2half_rn(v3.x), __float2half_rn(v3.y));
    __half2 h7 = __halves2half2(__float2half_rn(v3.z), __float2half_rn(v3.w));

    float4 o0, o1;
    o0.x = __uint_as_float(*(uint32_t*)&h0);
    o0.y = __uint_as_float(*(uint32_t*)&h1);
    o0.z = __uint_as_float(*(uint32_t*)&h2);
    o0.w = __uint_as_float(*(uint32_t*)&h3);
    o1.x = __uint_as_float(*(uint32_t*)&h4);
    o1.y = __uint_as_float(*(uint32_t*)&h5);
    o1.z = __uint_as_float(*(uint32_t*)&h6);
    o1.w = __uint_as_float(*(uint32_t*)&h7);
    dst[0] = o0;
    dst[1] = o1;
}

// ---------------------------------------------------------------------------
// Kernel 2: fp16 GEMM — 128x128x128 stages, 256 thr, 1 CTA/SM, 7 waves.
// ---------------------------------------------------------------------------
__global__ void __launch_bounds__(256, 1) fp16_gemm_kernel(
    float* __restrict__ out,
    const float* __restrict__ bias,
    const __half* __restrict__ xh,
    const __half* __restrict__ wh)
{
    extern __shared__ __align__(1024) char smem[];
    const uint32_t sb = smem_u32(smem);

    const int tid = threadIdx.x;
    const int lane = tid & 31;
    const int wid = tid >> 5;
    const int warp_m = wid >> 1;   // 0..3 (32 rows each)
    const int warp_n = wid & 1;    // 0..1 (64 cols each)

    const int n_tile = blockIdx.x & (N_TILES - 1);
    const int m_tile = blockIdx.x >> 4;
    const int m0 = m_tile * MT;
    const int n0 = n_tile * NT;

    // ---- loader: 256 thr; per 16KB half-subtile: 1024 chunks -> 4/thread ----
    // lrow = tid>>3 (0..31), rows r = lrow + i*32 (i=0..3), chunk = tid&7.
    // swizzle term i-invariant: (r+32)&7 == r&7.
    const int lrow = tid >> 3;
    const int lchk = tid & 7;
    const uint32_t dsw0 = (uint32_t)(lrow * 128 + ((lchk ^ (lrow & 7)) << 4));
    const __half* gA0 = xh + (size_t)(m0 + lrow) * K_TOTAL + lchk * 8;
    const __half* gB0 = wh + (size_t)(n0 + lrow) * K_TOTAL + lchk * 8;

    auto load_stage = [&](int stage, int k0) {
        uint32_t sbase = sb + stage * STAGE_BYTES + dsw0;
#pragma unroll
        for (int h = 0; h < 2; h++) {
            const __half* pA = gA0 + k0 + h * 64;
            const __half* pB = gB0 + k0 + h * 64;
#pragma unroll
            for (int i = 0; i < 4; i++) {
                cp_async16(sbase + h * HALF_BYTES + i * 4096,
                           pA + (size_t)i * (32 * K_TOTAL));
                cp_async16(sbase + OFF_B + h * HALF_BYTES + i * 4096,
                           pB + (size_t)i * (32 * K_TOTAL));
            }
        }
    };

    // ---- ldmatrix per-lane base terms ----
    const int a_row_l = warp_m * 32 + (lane & 15);
    const int a_kadd  = lane >> 4;
    const int b_row_l = warp_n * 64 + (lane & 7) + ((lane >> 4) << 3);
    const int b_kadd  = (lane >> 3) & 1;

    float acc[2][8][4];
#pragma unroll
    for (int mt = 0; mt < 2; mt++)
#pragma unroll
        for (int nt = 0; nt < 8; nt++)
#pragma unroll
            for (int j = 0; j < 4; j++) acc[mt][nt][j] = 0.0f;

    // ---- prologue ----
    load_stage(0, 0);
    CP_COMMIT();
    load_stage(1, KT);
    CP_COMMIT();

    uint32_t a[2][4], b[8][2];

    // kc = 0..7: half = kc>>2, sub-chunk kk = kc&3
    auto ld_frags = [&](int kc, uint32_t sbase) {
        uint32_t sA = sbase + (uint32_t)(kc >> 2) * HALF_BYTES;
        uint32_t sB = sA + OFF_B;
        int kk = kc & 3;
#pragma unroll
        for (int mt = 0; mt < 2; mt++) {
            int row = a_row_l + mt * 16;
            int ch = kk * 2 + a_kadd;
            uint32_t off = (uint32_t)(row * 128 + ((ch ^ (row & 7)) << 4));
            ldsm_x4(a[mt], sA + off);
        }
#pragma unroll
        for (int np = 0; np < 4; np++) {
            int row = b_row_l + np * 16;
            int ch = kk * 2 + b_kadd;
            uint32_t off = (uint32_t)(row * 128 + ((ch ^ (row & 7)) << 4));
            uint32_t t[4];
            ldsm_x4(t, sB + off);
            b[np * 2][0] = t[0]; b[np * 2][1] = t[1];
            b[np * 2 + 1][0] = t[2]; b[np * 2 + 1][1] = t[3];
        }
    };

    // ---- mainloop: 16 iterations, 8 kc chunks each ----
    for (int ks = 0; ks < KITERS; ks++) {
        CP_WAIT1();
        __syncthreads();

        const uint32_t sbase = sb + (ks % NSTAGE) * STAGE_BYTES;

        // kc0 frag loads first: cp.async burst runs in their shadow
        ld_frags(0, sbase);

        if (ks + 2 < KITERS) load_stage((ks + 2) % NSTAGE, (ks + 2) * KT);
        CP_COMMIT();

#pragma unroll
        for (int kc = 0; kc < 8; kc++) {
#pragma unroll
            for (int mt = 0; mt < 2; mt++) {
#pragma unroll
                for (int nt = 0; nt < 8; nt++) {
                    mma16816(acc[mt][nt], a[mt], b[nt]);
                }
            }
            if (kc < 7) ld_frags(kc + 1, sbase);
        }
    }

    // ---- epilogue: bias + store ----
    const int r0 = lane >> 2;
    const int c0 = (lane & 3) * 2;
#pragma unroll
    for (int mt = 0; mt < 2; mt++) {
        int row = m0 + warp_m * 32 + mt * 16 + r0;
#pragma unroll
        for (int nt = 0; nt < 8; nt++) {
            int col = n0 + warp_n * 64 + nt * 8 + c0;
            float bx = __ldg(bias + col);
            float by = __ldg(bias + col + 1);
            float2 v0 = make_float2(acc[mt][nt][0] + bx, acc[mt][nt][1] + by);
            float2 v1 = make_float2(acc[mt][nt][2] + bx, acc[mt][nt][3] + by);
            *(float2*)(out + (size_t)row * N_TOTAL + col) = v0;
            *(float2*)(out + (size_t)(row + 8) * N_TOTAL + col) = v1;
        }
    }
}

// ---------------------------------------------------------------------------
// Host side
// ---------------------------------------------------------------------------
extern "C" void kernel_launch(void* const* d_in, const int* in_sizes, int n_in,
                              void* d_out, int out_size) {
    const float* x    = (const float*)d_in[0];
    const float* w    = (const float*)d_in[1];
    const float* bias = (const float*)d_in[2];
    float* out = (float*)d_out;

    __half *xh, *wh;
    cudaGetSymbolAddress((void**)&xh, g_xh);
    cudaGetSymbolAddress((void**)&wh, g_wh);

    {
        int n16x = (M_TOTAL * K_TOTAL) / 16;   // 1,048,576
        int n16w = (N_TOTAL * K_TOTAL) / 16;   //   262,144
        int total = n16x + n16w;
        convert_both_kernel<<<(total + 255) / 256, 256>>>(
            (const float4*)x, (float4*)xh, n16x,
            (const float4*)w, (float4*)wh, n16w);
    }

    static bool attr_set = false;
    if (!attr_set) {
        cudaFuncSetAttribute(fp16_gemm_kernel,
                             cudaFuncAttributeMaxDynamicSharedMemorySize, SMEM_REQ);
        attr_set = true;
    }
    fp16_gemm_kernel<<<M_TILES * N_TILES, 256, SMEM_REQ>>>(out, bias, xh, wh);
}

// round 11
// speedup vs baseline: 1.0531x; 1.0531x over previous
#include <cuda_runtime.h>
#include <cuda_fp16.h>
#include <cstdint>

// ============================================================================
// out[8192,2048] = x[8192,2048] @ W[2048,2048]^T + bias
// fp16 single-term GEMM on HMMA (mma.sync m16n8k16.f32.f16.f16.f32).
// R11: intra-CTA split-K, named-barrier dual pipelines.
//   Grid 1024 (1 CTA/SM -> 7 waves, 1.2% quant loss vs R9's 13.5%).
//   256 thr = 2 independent 128-thr groups; group g covers k in
//   [g*1024,(g+1)*1024) with its own 3-stage cp.async pipeline (96KB) and
//   own named barrier -> groups free-run like 2 CTAs (2 warps/SMSP cover).
//   Warp tile 64x64 per group (R9 geometry + stage-head reorder).
//   Epilogue: cross-group partial add via smem, split evenly by warp_n.
// ============================================================================

#define M_TOTAL 8192
#define N_TOTAL 2048
#define K_TOTAL 2048

#define MT 128
#define NT 128
#define KT 64
#define K_GROUP 1024            // K per group
#define KITERS (K_GROUP / KT)   // 16 per group
#define NSTAGE 3

#define M_TILES (M_TOTAL / MT)  // 64
#define N_TILES (N_TOTAL / NT)  // 16

#define OFF_A 0
#define OFF_B 16384
#define STAGE_BYTES 32768
#define GROUP_SMEM (NSTAGE * STAGE_BYTES)   // 98304
#define SMEM_REQ (2 * GROUP_SMEM)           // 196608

__device__ __half g_xh[M_TOTAL * K_TOTAL];
__device__ __half g_wh[N_TOTAL * K_TOTAL];

// ---------------------------------------------------------------------------
__device__ __forceinline__ uint32_t smem_u32(const void* p) {
    uint32_t a;
    asm("{ .reg .u64 t; cvta.to.shared.u64 t, %1; cvt.u32.u64 %0, t; }"
        : "=r"(a) : "l"(p));
    return a;
}

__device__ __forceinline__ void cp_async16(uint32_t dst, const void* src) {
    asm volatile("cp.async.cg.shared.global [%0], [%1], 16;"
                 :: "r"(dst), "l"(src));
}
#define CP_COMMIT() asm volatile("cp.async.commit_group;" ::: "memory")
#define CP_WAIT1()  asm volatile("cp.async.wait_group 1;" ::: "memory")

#define BAR_SYNC(id) \
    asm volatile("bar.sync %0, 128;" :: "r"(id) : "memory")

__device__ __forceinline__ void ldsm_x4(uint32_t* r, uint32_t addr) {
    asm volatile("ldmatrix.sync.aligned.m8n8.x4.shared.b16 {%0,%1,%2,%3}, [%4];"
                 : "=r"(r[0]), "=r"(r[1]), "=r"(r[2]), "=r"(r[3])
                 : "r"(addr));
}

__device__ __forceinline__ void mma16816(float* c, const uint32_t* a, const uint32_t* b) {
    asm volatile(
        "mma.sync.aligned.m16n8k16.row.col.f32.f16.f16.f32 "
        "{%0,%1,%2,%3}, {%4,%5,%6,%7}, {%8,%9}, {%0,%1,%2,%3};"
        : "+f"(c[0]), "+f"(c[1]), "+f"(c[2]), "+f"(c[3])
        : "r"(a[0]), "r"(a[1]), "r"(a[2]), "r"(a[3]),
          "r"(b[0]), "r"(b[1]));
}

// ---------------------------------------------------------------------------
// Kernel 1: convert fp32 -> fp16 for BOTH x and W in one launch.
// ---------------------------------------------------------------------------
__global__ void __launch_bounds__(256) convert_both_kernel(
    const float4* __restrict__ srcx, float4* __restrict__ dstx, int n16x,
    const float4* __restrict__ srcw, float4* __restrict__ dstw, int n16w)
{
    int i = blockIdx.x * blockDim.x + threadIdx.x;
    const float4* src;
    float4* dst;
    if (i < n16x) {
        src = srcx + 4 * (size_t)i;
        dst = dstx + 2 * (size_t)i;
    } else {
        int j = i - n16x;
        if (j >= n16w) return;
        src = srcw + 4 * (size_t)j;
        dst = dstw + 2 * (size_t)j;
    }
    float4 v0 = src[0];
    float4 v1 = src[1];
    float4 v2 = src[2];
    float4 v3 = src[3];

    __half2 h0 = __halves2half2(__float2half_rn(v0.x), __float2half_rn(v0.y));
    __half2 h1 = __halves2half2(__float2half_rn(v0.z), __float2half_rn(v0.w));
    __half2 h2 = __halves2half2(__float2half_rn(v1.x), __float2half_rn(v1.y));
    __half2 h3 = __halves2half2(__float2half_rn(v1.z), __float2half_rn(v1.w));
    __half2 h4 = __halves2half2(__float2half_rn(v2.x), __float2half_rn(v2.y));
    __half2 h5 = __halves2half2(__float2half_rn(v2.z), __float2half_rn(v2.w));
    __half2 h6 = __halves2half2(__float2half_rn(v3.x), __float2half_rn(v3.y));
    __half2 h7 = __halves2half2(__float2half_rn(v3.z), __float2half_rn(v3.w));

    float4 o0, o1;
    o0.x = __uint_as_float(*(uint32_t*)&h0);
    o0.y = __uint_as_float(*(uint32_t*)&h1);
    o0.z = __uint_as_float(*(uint32_t*)&h2);
    o0.w = __uint_as_float(*(uint32_t*)&h3);
    o1.x = __uint_as_float(*(uint32_t*)&h4);
    o1.y = __uint_as_float(*(uint32_t*)&h5);
    o1.z = __uint_as_float(*(uint32_t*)&h6);
    o1.w = __uint_as_float(*(uint32_t*)&h7);
    dst[0] = o0;
    dst[1] = o1;
}

// ---------------------------------------------------------------------------
// Kernel 2: fp16 GEMM — dual independent 128-thread k-split pipelines.
// ---------------------------------------------------------------------------
__global__ void __launch_bounds__(256, 1) fp16_gemm_kernel(
    float* __restrict__ out,
    const float* __restrict__ bias,
    const __half* __restrict__ xh,
    const __half* __restrict__ wh)
{
    extern __shared__ __align__(1024) char smem[];
    const uint32_t sb = smem_u32(smem);

    const int tid = threadIdx.x;
    const int g = tid >> 7;            // group 0 / 1
    const int wg_tid = tid & 127;
    const int lane = wg_tid & 31;
    const int wid = wg_tid >> 5;       // 0..3 within group
    const int warp_m = wid >> 1;       // 0..1
    const int warp_n = wid & 1;        // 0..1

    const int n_tile = blockIdx.x & (N_TILES - 1);
    const int m_tile = blockIdx.x >> 4;
    const int m0 = m_tile * MT;
    const int n0 = n_tile * NT;

    const uint32_t gbase = sb + (uint32_t)g * GROUP_SMEM;
    const int k_base = g * K_GROUP;
    const int bar_id = g + 1;

    // ---- loader (per group: 128 threads, R9 layout) ----
    const int lrow = wg_tid >> 3;      // 0..15
    const int lchk = wg_tid & 7;
    const uint32_t dsw0 = (uint32_t)(lrow * 128 + ((lchk ^ (lrow & 7)) << 4));
    const __half* gA0 = xh + (size_t)(m0 + lrow) * K_TOTAL + k_base + lchk * 8;
    const __half* gB0 = wh + (size_t)(n0 + lrow) * K_TOTAL + k_base + lchk * 8;

    auto load_stage = [&](int stage, int k0) {
        uint32_t sbase = gbase + stage * STAGE_BYTES + dsw0;
        const __half* pA = gA0 + k0;
        const __half* pB = gB0 + k0;
#pragma unroll
        for (int i = 0; i < 8; i++) {
            cp_async16(sbase + OFF_A + i * 2048, pA + (size_t)i * (16 * K_TOTAL));
            cp_async16(sbase + OFF_B + i * 2048, pB + (size_t)i * (16 * K_TOTAL));
        }
    };

    // ---- ldmatrix per-lane base terms ----
    const int a_row_l = warp_m * 64 + (lane & 15);
    const int a_kadd  = lane >> 4;
    const int b_row_l = warp_n * 64 + (lane & 7) + ((lane >> 4) << 3);
    const int b_kadd  = (lane >> 3) & 1;

    float acc[4][8][4];
#pragma unroll
    for (int mt = 0; mt < 4; mt++)
#pragma unroll
        for (int nt = 0; nt < 8; nt++)
#pragma unroll
            for (int j = 0; j < 4; j++) acc[mt][nt][j] = 0.0f;

    // ---- prologue ----
    load_stage(0, 0);
    CP_COMMIT();
    load_stage(1, KT);
    CP_COMMIT();

    uint32_t a[4][4], b[8][2];

    auto ld_frags = [&](int kc, uint32_t sA, uint32_t sB) {
#pragma unroll
        for (int mt = 0; mt < 4; mt++) {
            int row = a_row_l + mt * 16;
            int ch = kc * 2 + a_kadd;
            uint32_t off = (uint32_t)(row * 128 + ((ch ^ (row & 7)) << 4));
            ldsm_x4(a[mt], sA + off);
        }
#pragma unroll
        for (int np = 0; np < 4; np++) {
            int row = b_row_l + np * 16;
            int ch = kc * 2 + b_kadd;
            uint32_t off = (uint32_t)(row * 128 + ((ch ^ (row & 7)) << 4));
            uint32_t t[4];
            ldsm_x4(t, sB + off);
            b[np * 2][0] = t[0]; b[np * 2][1] = t[1];
            b[np * 2 + 1][0] = t[2]; b[np * 2 + 1][1] = t[3];
        }
    };

    // ---- mainloop (independent per group; named barrier) ----
    for (int ks = 0; ks < KITERS; ks++) {
        CP_WAIT1();
        BAR_SYNC(bar_id);

        const uint32_t sbase = gbase + (ks % NSTAGE) * STAGE_BYTES;
        const uint32_t sA = sbase + OFF_A;
        const uint32_t sB = sbase + OFF_B;

        // kc0 frag loads first: cp.async burst runs in their shadow
        ld_frags(0, sA, sB);

        if (ks + 2 < KITERS) load_stage((ks + 2) % NSTAGE, (ks + 2) * KT);
        CP_COMMIT();

#pragma unroll
        for (int kc = 0; kc < 4; kc++) {
#pragma unroll
            for (int mt = 0; mt < 4; mt++) {
#pragma unroll
                for (int nt = 0; nt < 8; nt++) {
                    mma16816(acc[mt][nt], a[mt], b[nt]);
                }
            }
            if (kc < 3) ld_frags(kc + 1, sA, sB);
        }
    }

    // ---- epilogue: cross-group partial reduction via smem ----
    // writers:  (g==0 && warp_n==1) or (g==1 && warp_n==0)
    // readers:  (g==0 && warp_n==0) or (g==1 && warp_n==1)
    // Both cover quadrants (warp_m, warp_n); writer and reader of the same
    // quadrant hold identical lane->element maps, so positions line up.
    __syncthreads();   // both groups done; group-0 pipeline smem now dead

    float* sp = (float*)smem;   // 128x128 fp32 partial tile (64KB)
    const int r0 = lane >> 2;
    const int c0 = (lane & 3) * 2;
    const bool writer = (warp_n ^ g) != 0;

    if (writer) {
#pragma unroll
        for (int mt = 0; mt < 4; mt++) {
            int row_l = warp_m * 64 + mt * 16 + r0;
#pragma unroll
            for (int nt = 0; nt < 8; nt++) {
                int col_l = warp_n * 64 + nt * 8 + c0;
                *(float2*)(sp + row_l * 128 + col_l) =
                    make_float2(acc[mt][nt][0], acc[mt][nt][1]);
                *(float2*)(sp + (row_l + 8) * 128 + col_l) =
                    make_float2(acc[mt][nt][2], acc[mt][nt][3]);
            }
        }
    }
    __syncthreads();

    if (!writer) {
#pragma unroll
        for (int mt = 0; mt < 4; mt++) {
            int row_l = warp_m * 64 + mt * 16 + r0;
            int row = m0 + row_l;
#pragma unroll
            for (int nt = 0; nt < 8; nt++) {
                int col_l = warp_n * 64 + nt * 8 + c0;
                int col = n0 + col_l;
                float bx = __ldg(bias + col);
                float by = __ldg(bias + col + 1);
                float2 p0 = *(float2*)(sp + row_l * 128 + col_l);
                float2 p1 = *(float2*)(sp + (row_l + 8) * 128 + col_l);
                float2 v0 = make_float2(acc[mt][nt][0] + p0.x + bx,
                                        acc[mt][nt][1] + p0.y + by);
                float2 v1 = make_float2(acc[mt][nt][2] + p1.x + bx,
                                        acc[mt][nt][3] + p1.y + by);
                *(float2*)(out + (size_t)row * N_TOTAL + col) = v0;
                *(float2*)(out + (size_t)(row + 8) * N_TOTAL + col) = v1;
            }
        }
    }
}

// ---------------------------------------------------------------------------
// Host side
// ---------------------------------------------------------------------------
extern "C" void kernel_launch(void* const* d_in, const int* in_sizes, int n_in,
                              void* d_out, int out_size) {
    const float* x    = (const float*)d_in[0];
    const float* w    = (const float*)d_in[1];
    const float* bias = (const float*)d_in[2];
    float* out = (float*)d_out;

    __half *xh, *wh;
    cudaGetSymbolAddress((void**)&xh, g_xh);
    cudaGetSymbolAddress((void**)&wh, g_wh);

    {
        int n16x = (M_TOTAL * K_TOTAL) / 16;   // 1,048,576
        int n16w = (N_TOTAL * K_TOTAL) / 16;   //   262,144
        int total = n16x + n16w;
        convert_both_kernel<<<(total + 255) / 256, 256>>>(
            (const float4*)x, (float4*)xh, n16x,
            (const float4*)w, (float4*)wh, n16w);
    }

    static bool attr_set = false;
    if (!attr_set) {
        cudaFuncSetAttribute(fp16_gemm_kernel,
                             cudaFuncAttributeMaxDynamicSharedMemorySize, SMEM_REQ);
        attr_set = true;
    }
    fp16_gemm_kernel<<<M_TILES * N_TILES, 256, SMEM_REQ>>>(out, bias, xh, wh);
}